// round 12
// baseline (speedup 1.0000x reference)
#include <cuda_runtime.h>
#include <cuda_bf16.h>
#include <mma.h>
#include <math.h>
#include <stdint.h>

using namespace nvcuda;

// LinearSelfAttention: B=4, T=8192, D=512, H=8, HD=64
// Round-11 PASS (1030us) + TRUE software pipelining in K1/K5:
// LDG (chunk c+1) -> registers BEFORE MMA(chunk c); convert+STS AFTER MMA.
// This lets tensor work cover global-load latency (round-11's version
// serialized LDG->cvt->STS ahead of the MMAs in program order).

#define B_ 4
#define T_ 8192
#define D_ 512
#define H_ 8
#define HD_ 64
#define TT_ 128            // token tile
#define NTILE_ (T_ / TT_)  // 64
#define KC_ 32             // k-chunk
#define NCH_ (D_ / KC_)    // 16
#define LDS_ 48            // smem row stride in bf16 (96B rows)

// ---------------- scratch (device globals; no allocs) ----------------
__device__ __align__(128) float g_Upart[B_ * NTILE_ * H_ * HD_ * HD_]; // 32 MB
__device__ __align__(128) float g_Spart[B_ * NTILE_ * H_ * HD_];
__device__ __align__(128) float g_C[B_ * H_ * HD_ * HD_];
__device__ __align__(128) float g_A[B_ * D_ * D_];
__device__ __align__(128) float g_Et[B_ * D_ * D_];                    // E^T [b][o][i]
__device__ __align__(128) float g_pb[B_ * D_];
__device__ __align__(128) float g_bias[B_ * D_];

#define TILE_BYTES_ (128 * LDS_ * 2)                       // 12288
#define BTOFF_(s, t4) ((uint32_t)(s) * (4 * TILE_BYTES_) + (uint32_t)(t4) * TILE_BYTES_)
#define WSMEM_ (2 * 4 * TILE_BYTES_)                       // 98304

typedef wmma::fragment<wmma::matrix_a, 16, 16, 16, __nv_bfloat16, wmma::row_major> FragA;
typedef wmma::fragment<wmma::matrix_b, 16, 16, 16, __nv_bfloat16, wmma::col_major> FragB;
typedef wmma::fragment<wmma::accumulator, 16, 16, 16, float> FragC;

// convert float4 -> bf16 hi/lo pairs and store 8B each
__device__ __forceinline__ void split_store(__nv_bfloat16* Hi, __nv_bfloat16* Lo,
                                            int e, float4 v)
{
    __nv_bfloat162 h0 = __floats2bfloat162_rn(v.x, v.y);
    __nv_bfloat162 h1 = __floats2bfloat162_rn(v.z, v.w);
    __nv_bfloat162 l0 = __floats2bfloat162_rn(v.x - __low2float(h0), v.y - __high2float(h0));
    __nv_bfloat162 l1 = __floats2bfloat162_rn(v.z - __low2float(h1), v.w - __high2float(h1));
    *reinterpret_cast<__nv_bfloat162*>(Hi + e)     = h0;
    *reinterpret_cast<__nv_bfloat162*>(Hi + e + 2) = h1;
    *reinterpret_cast<__nv_bfloat162*>(Lo + e)     = l0;
    *reinterpret_cast<__nv_bfloat162*>(Lo + e + 2) = l1;
}

// shared MMA inner block for one staged buffer
__device__ __forceinline__ void mma_chunk(const char* smem, int s, int m0, int n0,
                                          FragC acc[2][4])
{
    const __nv_bfloat16* Ah = reinterpret_cast<const __nv_bfloat16*>(smem + BTOFF_(s, 0));
    const __nv_bfloat16* Al = reinterpret_cast<const __nv_bfloat16*>(smem + BTOFF_(s, 1));
    const __nv_bfloat16* Bh = reinterpret_cast<const __nv_bfloat16*>(smem + BTOFF_(s, 2));
    const __nv_bfloat16* Bl = reinterpret_cast<const __nv_bfloat16*>(smem + BTOFF_(s, 3));
    #pragma unroll
    for (int ks = 0; ks < KC_; ks += 16) {
        FragA fah[2], fal[2];
        FragB fbh[4], fbl[4];
        #pragma unroll
        for (int mt = 0; mt < 2; mt++) {
            wmma::load_matrix_sync(fah[mt], Ah + (m0 + mt * 16) * LDS_ + ks, LDS_);
            wmma::load_matrix_sync(fal[mt], Al + (m0 + mt * 16) * LDS_ + ks, LDS_);
        }
        #pragma unroll
        for (int nt = 0; nt < 4; nt++) {
            wmma::load_matrix_sync(fbh[nt], Bh + (n0 + nt * 16) * LDS_ + ks, LDS_);
            wmma::load_matrix_sync(fbl[nt], Bl + (n0 + nt * 16) * LDS_ + ks, LDS_);
        }
        #pragma unroll
        for (int mt = 0; mt < 2; mt++)
            #pragma unroll
            for (int nt = 0; nt < 4; nt++) {
                wmma::mma_sync(acc[mt][nt], fah[mt], fbh[nt], acc[mt][nt]);
                wmma::mma_sync(acc[mt][nt], fah[mt], fbl[nt], acc[mt][nt]);
                wmma::mma_sync(acc[mt][nt], fal[mt], fbh[nt], acc[mt][nt]);
            }
    }
}

// =====================================================================
// K1: WMMA split-bf16 KV projection + exp + U/S. Register-pipelined.
// grid (64 tiles, 8 heads, 4 b), block 256 (8 warps, warp tile 32x64).
// =====================================================================
__global__ __launch_bounds__(256)
void k1_kv_context(const float* __restrict__ x,
                   const float* __restrict__ Wqkv,
                   const float* __restrict__ bqkv)
{
    extern __shared__ __align__(128) char smem[];
    const int tid = threadIdx.x, wid = tid >> 5;
    const int tile = blockIdx.x, h = blockIdx.y, b = blockIdx.z;
    const float* xb = x + (size_t)(b * T_ + tile * TT_) * D_;
    const int wrow_k = D_ + h * HD_;
    const int wrow_v = 2 * D_ + h * HD_;

    const int m0 = (wid >> 1) * 32;
    const int n0 = (wid & 1) * 64;

    FragC acc[2][4];
    #pragma unroll
    for (int mt = 0; mt < 2; mt++)
        #pragma unroll
        for (int nt = 0; nt < 4; nt++) wmma::fill_fragment(acc[mt][nt], 0.f);

    float4 xv[4], wv[4];

    auto load_regs = [&](int c) {
        const int k0 = c * KC_;
        #pragma unroll
        for (int q = 0; q < 4; q++) {
            int flat = q * 256 + tid;
            int r = flat >> 3, j = flat & 7;
            xv[q] = *reinterpret_cast<const float4*>(xb + (size_t)r * D_ + k0 + j * 4);
        }
        #pragma unroll
        for (int q = 0; q < 4; q++) {
            int flat = q * 256 + tid;
            int col = flat >> 3, j = flat & 7;
            int wrow = (col < 64) ? (wrow_k + col) : (wrow_v + col - 64);
            wv[q] = *reinterpret_cast<const float4*>(Wqkv + (size_t)wrow * D_ + k0 + j * 4);
        }
    };
    auto store_regs = [&](int s) {
        __nv_bfloat16* Ah = reinterpret_cast<__nv_bfloat16*>(smem + BTOFF_(s, 0));
        __nv_bfloat16* Al = reinterpret_cast<__nv_bfloat16*>(smem + BTOFF_(s, 1));
        __nv_bfloat16* Bh = reinterpret_cast<__nv_bfloat16*>(smem + BTOFF_(s, 2));
        __nv_bfloat16* Bl = reinterpret_cast<__nv_bfloat16*>(smem + BTOFF_(s, 3));
        #pragma unroll
        for (int q = 0; q < 4; q++) {
            int flat = q * 256 + tid;
            int r = flat >> 3, j = flat & 7;
            split_store(Ah, Al, r * LDS_ + j * 4, xv[q]);
        }
        #pragma unroll
        for (int q = 0; q < 4; q++) {
            int flat = q * 256 + tid;
            int col = flat >> 3, j = flat & 7;
            split_store(Bh, Bl, col * LDS_ + j * 4, wv[q]);
        }
    };

    load_regs(0);
    store_regs(0);
    __syncthreads();

    for (int c = 0; c < NCH_; c++) {
        const int s = c & 1;
        if (c + 1 < NCH_) load_regs(c + 1);      // LDGs in flight during MMA
        mma_chunk(smem, s, m0, n0, acc);
        if (c + 1 < NCH_) store_regs(s ^ 1);     // consume after MMA
        __syncthreads();
    }

    // epilogue: acc -> KV smem [128][132] fp32
    float* KV = reinterpret_cast<float*>(smem);
    #pragma unroll
    for (int mt = 0; mt < 2; mt++)
        #pragma unroll
        for (int nt = 0; nt < 4; nt++)
            wmma::store_matrix_sync(KV + (m0 + mt * 16) * 132 + n0 + nt * 16,
                                    acc[mt][nt], 132, wmma::mem_row_major);
    __syncthreads();

    // bias + exp on k-half
    #pragma unroll
    for (int i = 0; i < 64; i++) {
        int flat = i * 256 + tid;
        int r = flat >> 7, cc = flat & 127;
        float v = KV[r * 132 + cc];
        if (cc < 64) v = expf(v + bqkv[wrow_k + cc]);
        else         v = v + bqkv[wrow_v + cc - 64];
        KV[r * 132 + cc] = v;
    }
    __syncthreads();

    // U = EK^T @ V (16x16 threads, 4x4 micro)
    const int tx = tid & 15, ty = tid >> 4;
    float u[4][4];
    #pragma unroll
    for (int dd = 0; dd < 4; dd++)
        #pragma unroll
        for (int vv = 0; vv < 4; vv++) u[dd][vv] = 0.f;
    for (int t = 0; t < TT_; t++) {
        float a_[4], b_[4];
        #pragma unroll
        for (int dd = 0; dd < 4; dd++) a_[dd] = KV[t * 132 + ty * 4 + dd];
        #pragma unroll
        for (int vv = 0; vv < 4; vv++) b_[vv] = KV[t * 132 + 64 + tx * 4 + vv];
        #pragma unroll
        for (int dd = 0; dd < 4; dd++)
            #pragma unroll
            for (int vv = 0; vv < 4; vv++) u[dd][vv] += a_[dd] * b_[vv];
    }
    size_t ubase = (size_t)((b * NTILE_ + tile) * H_ + h) * (HD_ * HD_);
    #pragma unroll
    for (int dd = 0; dd < 4; dd++)
        #pragma unroll
        for (int vv = 0; vv < 4; vv++)
            g_Upart[ubase + (ty * 4 + dd) * HD_ + tx * 4 + vv] = u[dd][vv];
    if (tid < 64) {
        float ssum = 0.f;
        for (int t = 0; t < TT_; t++) ssum += KV[t * 132 + tid];
        g_Spart[((b * NTILE_ + tile) * H_ + h) * HD_ + tid] = ssum;
    }
}

// =====================================================================
// K2: reduce partials -> C = U / S  (unchanged)
// =====================================================================
__global__ void k2_reduce()
{
    const int b = blockIdx.x >> 3, h = blockIdx.x & 7;
    const int tid = threadIdx.x;
    __shared__ float S[64];
    if (tid < 64) {
        float s = 0.f;
        for (int t = 0; t < NTILE_; t++)
            s += g_Spart[((b * NTILE_ + t) * H_ + h) * HD_ + tid];
        S[tid] = s;
    }
    __syncthreads();
    for (int e = tid; e < HD_ * HD_; e += 256) {
        float u = 0.f;
        #pragma unroll 8
        for (int t = 0; t < NTILE_; t++)
            u += g_Upart[(size_t)((b * NTILE_ + t) * H_ + h) * (HD_ * HD_) + e];
        g_C[(b * H_ + h) * (HD_ * HD_) + e] = u / S[e >> 6];
    }
}

// =====================================================================
// K3: A[b][j][i]  (unchanged)
// =====================================================================
__global__ void k3_A(const float* __restrict__ Wqkv)
{
    const int b = blockIdx.x >> 3, h = blockIdx.x & 7;
    const int tid = threadIdx.x;
    __shared__ float Ch[64 * 64];
    __shared__ float Wc[64 * 128];
    for (int e = tid; e < 4096; e += 256)
        Ch[e] = g_C[(b * H_ + h) * 4096 + e];
    for (int chunk = 0; chunk < 4; chunk++) {
        int i0 = chunk * 128;
        __syncthreads();
        for (int e = tid; e < 64 * 128; e += 256) {
            int d = e >> 7, ii = e & 127;
            Wc[e] = Wqkv[(size_t)(h * HD_ + d) * D_ + i0 + ii];
        }
        __syncthreads();
        for (int idx = tid; idx < 64 * 128; idx += 256) {
            int vv = idx >> 7, ii = idx & 127;
            float s = 0.f;
            #pragma unroll
            for (int d = 0; d < 64; d++) s += Ch[d * 64 + vv] * Wc[d * 128 + ii];
            g_A[(size_t)b * (D_ * D_) + (size_t)(h * HD_ + vv) * D_ + i0 + ii] = s;
        }
    }
}

__global__ void k3b_pb(const float* __restrict__ bqkv)
{
    const int b = blockIdx.x;
    const int j = threadIdx.x;
    const int h = j >> 6, vv = j & 63;
    float s = 0.f;
    for (int d = 0; d < 64; d++)
        s += bqkv[h * HD_ + d] * g_C[(b * H_ + h) * 4096 + d * 64 + vv];
    g_pb[b * D_ + j] = s;
}

// =====================================================================
// K4: E^T [b][o][i] fp32, float4 stores along i  (round-11 verbatim)
// =====================================================================
__global__ __launch_bounds__(256, 2)
void k4_E(const float* __restrict__ Wout)
{
    const int tid = threadIdx.x;
    const int tx = tid & 15, ty = tid >> 4;
    const int i0 = blockIdx.x * 128, o0 = blockIdx.y * 128, b = blockIdx.z;
    __shared__ float Xs[128 * 17];
    __shared__ float Ws[128 * 17];
    const float* Ab = g_A + (size_t)b * (D_ * D_);

    float acc[8][8];
    #pragma unroll
    for (int r = 0; r < 8; r++)
        #pragma unroll
        for (int c = 0; c < 8; c++) acc[r][c] = 0.f;

    for (int j0 = 0; j0 < D_; j0 += 16) {
        #pragma unroll
        for (int q = 0; q < 2; q++) {
            int flat = tid * 2 + q;
            int jj = flat >> 5;
            int ii = (flat & 31) * 4;
            float4 t = *reinterpret_cast<const float4*>(Ab + (size_t)(j0 + jj) * D_ + i0 + ii);
            Xs[(ii + 0) * 17 + jj] = t.x;
            Xs[(ii + 1) * 17 + jj] = t.y;
            Xs[(ii + 2) * 17 + jj] = t.z;
            Xs[(ii + 3) * 17 + jj] = t.w;
        }
        #pragma unroll
        for (int q = 0; q < 2; q++) {
            int flat = tid * 2 + q;
            int col = flat >> 2;
            int c4 = (flat & 3) * 4;
            float4 t = *reinterpret_cast<const float4*>(Wout + (size_t)(o0 + col) * D_ + j0 + c4);
            float* dst = Ws + col * 17 + c4;
            dst[0] = t.x; dst[1] = t.y; dst[2] = t.z; dst[3] = t.w;
        }
        __syncthreads();
        #pragma unroll
        for (int kk = 0; kk < 16; kk++) {
            float a_[8], b_[8];
            #pragma unroll
            for (int r = 0; r < 8; r++) a_[r] = Xs[(ty * 8 + r) * 17 + kk];
            #pragma unroll
            for (int c = 0; c < 8; c++) b_[c] = Ws[(tx + 16 * c) * 17 + kk];
            #pragma unroll
            for (int r = 0; r < 8; r++)
                #pragma unroll
                for (int c = 0; c < 8; c++) acc[r][c] += a_[r] * b_[c];
        }
        __syncthreads();
    }
    float* Eb = g_Et + (size_t)b * (D_ * D_);
    #pragma unroll
    for (int c = 0; c < 8; c++) {
        int o = o0 + tx + 16 * c;
        float4 v0 = make_float4(acc[0][c], acc[1][c], acc[2][c], acc[3][c]);
        float4 v1 = make_float4(acc[4][c], acc[5][c], acc[6][c], acc[7][c]);
        *reinterpret_cast<float4*>(Eb + (size_t)o * D_ + i0 + ty * 8)     = v0;
        *reinterpret_cast<float4*>(Eb + (size_t)o * D_ + i0 + ty * 8 + 4) = v1;
    }
}

__global__ void k4b_bias(const float* __restrict__ Wout, const float* __restrict__ bout)
{
    const int b = blockIdx.x;
    const int o = threadIdx.x;
    float s = bout[o];
    const float* wr = Wout + (size_t)o * D_;
    const float* pb = g_pb + b * D_;
    #pragma unroll 8
    for (int j = 0; j < D_; j++) s += pb[j] * wr[j];
    g_bias[b * D_ + o] = s;
}

// =====================================================================
// K5: out = x @ E_b + bias, WMMA split-bf16, register-pipelined.
// =====================================================================
__global__ __launch_bounds__(256)
void k5_out(const float* __restrict__ x, float* __restrict__ out)
{
    extern __shared__ __align__(128) char smem[];
    const int tid = threadIdx.x, wid = tid >> 5;
    const int t0 = blockIdx.x * TT_, o0 = blockIdx.y * 128, b = blockIdx.z;
    const float* xb = x + (size_t)(b * T_ + t0) * D_;
    const float* Eb = g_Et + (size_t)b * (D_ * D_);

    const int m0 = (wid >> 1) * 32;
    const int n0 = (wid & 1) * 64;

    FragC acc[2][4];
    #pragma unroll
    for (int mt = 0; mt < 2; mt++)
        #pragma unroll
        for (int nt = 0; nt < 4; nt++) wmma::fill_fragment(acc[mt][nt], 0.f);

    float4 xv[4], ev[4];

    auto load_regs = [&](int c) {
        const int k0 = c * KC_;
        #pragma unroll
        for (int q = 0; q < 4; q++) {
            int flat = q * 256 + tid;
            int r = flat >> 3, j = flat & 7;
            xv[q] = *reinterpret_cast<const float4*>(xb + (size_t)r * D_ + k0 + j * 4);
        }
        #pragma unroll
        for (int q = 0; q < 4; q++) {
            int flat = q * 256 + tid;
            int o = flat >> 3, j = flat & 7;
            ev[q] = *reinterpret_cast<const float4*>(Eb + (size_t)(o0 + o) * D_ + k0 + j * 4);
        }
    };
    auto store_regs = [&](int s) {
        __nv_bfloat16* Ah = reinterpret_cast<__nv_bfloat16*>(smem + BTOFF_(s, 0));
        __nv_bfloat16* Al = reinterpret_cast<__nv_bfloat16*>(smem + BTOFF_(s, 1));
        __nv_bfloat16* Bh = reinterpret_cast<__nv_bfloat16*>(smem + BTOFF_(s, 2));
        __nv_bfloat16* Bl = reinterpret_cast<__nv_bfloat16*>(smem + BTOFF_(s, 3));
        #pragma unroll
        for (int q = 0; q < 4; q++) {
            int flat = q * 256 + tid;
            int r = flat >> 3, j = flat & 7;
            split_store(Ah, Al, r * LDS_ + j * 4, xv[q]);
        }
        #pragma unroll
        for (int q = 0; q < 4; q++) {
            int flat = q * 256 + tid;
            int o = flat >> 3, j = flat & 7;
            split_store(Bh, Bl, o * LDS_ + j * 4, ev[q]);
        }
    };

    load_regs(0);
    store_regs(0);
    __syncthreads();

    for (int c = 0; c < NCH_; c++) {
        const int s = c & 1;
        if (c + 1 < NCH_) load_regs(c + 1);
        mma_chunk(smem, s, m0, n0, acc);
        if (c + 1 < NCH_) store_regs(s ^ 1);
        __syncthreads();
    }

    // epilogue: acc -> smem stage -> +bias -> coalesced fp32 stores
    float* Stage = reinterpret_cast<float*>(smem);   // [128][132]
    #pragma unroll
    for (int mt = 0; mt < 2; mt++)
        #pragma unroll
        for (int nt = 0; nt < 4; nt++)
            wmma::store_matrix_sync(Stage + (m0 + mt * 16) * 132 + n0 + nt * 16,
                                    acc[mt][nt], 132, wmma::mem_row_major);
    __syncthreads();

    #pragma unroll
    for (int q = 0; q < 16; q++) {
        int flat = q * 256 + tid;
        int r = flat >> 5, j = flat & 31;
        float4 v = *reinterpret_cast<const float4*>(Stage + r * 132 + j * 4);
        float4 bias = *reinterpret_cast<const float4*>(g_bias + b * D_ + o0 + j * 4);
        v.x += bias.x; v.y += bias.y; v.z += bias.z; v.w += bias.w;
        *reinterpret_cast<float4*>(out + (size_t)(b * T_ + t0 + r) * D_ + o0 + j * 4) = v;
    }
}

// =====================================================================
extern "C" void kernel_launch(void* const* d_in, const int* in_sizes, int n_in,
                              void* d_out, int out_size)
{
    (void)in_sizes; (void)n_in; (void)out_size;
    const float* x    = (const float*)d_in[0];
    const float* Wqkv = (const float*)d_in[1];
    const float* bqkv = (const float*)d_in[2];
    const float* Wout = (const float*)d_in[3];
    const float* bout = (const float*)d_in[4];
    float* out = (float*)d_out;

    cudaFuncSetAttribute(k1_kv_context, cudaFuncAttributeMaxDynamicSharedMemorySize, WSMEM_);
    cudaFuncSetAttribute(k5_out, cudaFuncAttributeMaxDynamicSharedMemorySize, WSMEM_);

    k1_kv_context<<<dim3(NTILE_, H_, B_), 256, WSMEM_>>>(x, Wqkv, bqkv);
    k2_reduce<<<B_ * H_, 256>>>();
    k3_A<<<B_ * H_, 256>>>(Wqkv);
    k3b_pb<<<B_, D_>>>(bqkv);
    k4_E<<<dim3(4, 4, B_), 256>>>(Wout);
    k4b_bias<<<B_, D_>>>(Wout, bout);
    k5_out<<<dim3(NTILE_, 4, B_), 256, WSMEM_>>>(x, out);
}

// round 15
// speedup vs baseline: 1.0644x; 1.0644x over previous
#include <cuda_runtime.h>
#include <cuda_bf16.h>
#include <cuda_pipeline.h>
#include <mma.h>
#include <math.h>
#include <stdint.h>

using namespace nvcuda;

// LinearSelfAttention: B=4, T=8192, D=512, H=8, HD=64
// Round-11 structure (1030us PASS) with conversion hoisted out of hot loops:
//  - Kx/K0: one-time bf16 hi/lo pre-split of x and W_kv
//  - K4: writes E^T [b][o][i] directly as bf16 hi/lo
//  - K1/K5: cp.async (__pipeline intrinsics) double-buffered staging of
//    pre-converted bf16 tiles; MMA core unchanged (proven rounds 9-12).

#define B_ 4
#define T_ 8192
#define D_ 512
#define H_ 8
#define HD_ 64
#define TT_ 128            // token tile
#define NTILE_ (T_ / TT_)  // 64
#define KC_ 32             // k-chunk
#define NCH_ (D_ / KC_)    // 16
#define LDS_ 48            // smem row stride in bf16 (96B rows)

// ---------------- scratch (device globals; no allocs) ----------------
__device__ __align__(128) __nv_bfloat16 g_xh[(size_t)B_ * T_ * D_];   // 32 MB
__device__ __align__(128) __nv_bfloat16 g_xl[(size_t)B_ * T_ * D_];   // 32 MB
__device__ __align__(128) __nv_bfloat16 g_Wh[1024 * D_];              // K rows then V rows
__device__ __align__(128) __nv_bfloat16 g_Wl[1024 * D_];
__device__ __align__(128) __nv_bfloat16 g_Eth[(size_t)B_ * D_ * D_];  // E^T [b][o][i] hi
__device__ __align__(128) __nv_bfloat16 g_Etl[(size_t)B_ * D_ * D_];  // E^T lo
__device__ __align__(128) float g_Upart[B_ * NTILE_ * H_ * HD_ * HD_];
__device__ __align__(128) float g_Spart[B_ * NTILE_ * H_ * HD_];
__device__ __align__(128) float g_C[B_ * H_ * HD_ * HD_];
__device__ __align__(128) float g_A[B_ * D_ * D_];
__device__ __align__(128) float g_pb[B_ * D_];
__device__ __align__(128) float g_bias[B_ * D_];

#define TILE_BYTES_ (128 * LDS_ * 2)                       // 12288
#define BTOFF_(s, t4) ((uint32_t)(s) * (4 * TILE_BYTES_) + (uint32_t)(t4) * TILE_BYTES_)
#define WSMEM_ (2 * 4 * TILE_BYTES_)                       // 98304

typedef wmma::fragment<wmma::matrix_a, 16, 16, 16, __nv_bfloat16, wmma::row_major> FragA;
typedef wmma::fragment<wmma::matrix_b, 16, 16, 16, __nv_bfloat16, wmma::col_major> FragB;
typedef wmma::fragment<wmma::accumulator, 16, 16, 16, float> FragC;

// shared MMA inner block for one staged buffer (proven rounds 9-12)
__device__ __forceinline__ void mma_chunk(const char* smem, int s, int m0, int n0,
                                          FragC acc[2][4])
{
    const __nv_bfloat16* Ah = reinterpret_cast<const __nv_bfloat16*>(smem + BTOFF_(s, 0));
    const __nv_bfloat16* Al = reinterpret_cast<const __nv_bfloat16*>(smem + BTOFF_(s, 1));
    const __nv_bfloat16* Bh = reinterpret_cast<const __nv_bfloat16*>(smem + BTOFF_(s, 2));
    const __nv_bfloat16* Bl = reinterpret_cast<const __nv_bfloat16*>(smem + BTOFF_(s, 3));
    #pragma unroll
    for (int ks = 0; ks < KC_; ks += 16) {
        FragA fah[2], fal[2];
        FragB fbh[4], fbl[4];
        #pragma unroll
        for (int mt = 0; mt < 2; mt++) {
            wmma::load_matrix_sync(fah[mt], Ah + (m0 + mt * 16) * LDS_ + ks, LDS_);
            wmma::load_matrix_sync(fal[mt], Al + (m0 + mt * 16) * LDS_ + ks, LDS_);
        }
        #pragma unroll
        for (int nt = 0; nt < 4; nt++) {
            wmma::load_matrix_sync(fbh[nt], Bh + (n0 + nt * 16) * LDS_ + ks, LDS_);
            wmma::load_matrix_sync(fbl[nt], Bl + (n0 + nt * 16) * LDS_ + ks, LDS_);
        }
        #pragma unroll
        for (int mt = 0; mt < 2; mt++)
            #pragma unroll
            for (int nt = 0; nt < 4; nt++) {
                wmma::mma_sync(acc[mt][nt], fah[mt], fbh[nt], acc[mt][nt]);
                wmma::mma_sync(acc[mt][nt], fah[mt], fbl[nt], acc[mt][nt]);
                wmma::mma_sync(acc[mt][nt], fal[mt], fbh[nt], acc[mt][nt]);
            }
    }
}

// =====================================================================
// Kx / K0: one-time fp32 -> bf16 hi/lo splits (proven store pattern)
// =====================================================================
__global__ void kx_xsplit(const float* __restrict__ x)
{
    size_t idx = ((size_t)blockIdx.x * 256 + threadIdx.x) * 4;
    float4 v = *reinterpret_cast<const float4*>(x + idx);
    __nv_bfloat162 h0 = __floats2bfloat162_rn(v.x, v.y);
    __nv_bfloat162 h1 = __floats2bfloat162_rn(v.z, v.w);
    __nv_bfloat162 l0 = __floats2bfloat162_rn(v.x - __low2float(h0), v.y - __high2float(h0));
    __nv_bfloat162 l1 = __floats2bfloat162_rn(v.z - __low2float(h1), v.w - __high2float(h1));
    *reinterpret_cast<__nv_bfloat162*>(g_xh + idx)     = h0;
    *reinterpret_cast<__nv_bfloat162*>(g_xh + idx + 2) = h1;
    *reinterpret_cast<__nv_bfloat162*>(g_xl + idx)     = l0;
    *reinterpret_cast<__nv_bfloat162*>(g_xl + idx + 2) = l1;
}

__global__ void k0_wsplit(const float* __restrict__ Wqkv)
{
    int idx = blockIdx.x * 256 + threadIdx.x;   // 1024*512 total
    int r = idx >> 9, c = idx & 511;
    int src = (r < 512) ? (D_ + r) : (2 * D_ + (r - 512));
    float w = Wqkv[(size_t)src * D_ + c];
    __nv_bfloat16 hi = __float2bfloat16(w);
    g_Wh[idx] = hi;
    g_Wl[idx] = __float2bfloat16(w - __bfloat162float(hi));
}

// =====================================================================
// K1: WMMA split-bf16 KV projection + exp + U/S. cp.async pipelined.
// grid (64 tiles, 8 heads, 4 b), block 256 (8 warps, warp tile 32x64).
// =====================================================================
__global__ __launch_bounds__(256)
void k1_kv_context(const float* __restrict__ bqkv)
{
    extern __shared__ __align__(128) char smem[];
    const int tid = threadIdx.x, wid = tid >> 5;
    const int tile = blockIdx.x, h = blockIdx.y, b = blockIdx.z;
    const size_t xrow0 = (size_t)(b * T_ + tile * TT_) * D_;
    const int wrow_k = D_ + h * HD_;
    const int wrow_v = 2 * D_ + h * HD_;

    const int m0 = (wid >> 1) * 32;
    const int n0 = (wid & 1) * 64;

    FragC acc[2][4];
    #pragma unroll
    for (int mt = 0; mt < 2; mt++)
        #pragma unroll
        for (int nt = 0; nt < 4; nt++) wmma::fill_fragment(acc[mt][nt], 0.f);

    auto prefetch = [&](int c, int s) {
        const int k0 = c * KC_;
        #pragma unroll
        for (int q = 0; q < 8; q++) {
            int flat = q * 256 + tid;          // 0..2047 16B-chunks
            int t4 = flat >> 9;
            int w = flat & 511;
            int r = w >> 2, j = w & 3;
            char* dst = smem + BTOFF_(s, t4) + (uint32_t)r * (LDS_ * 2) + (uint32_t)j * 16;
            const __nv_bfloat16* src;
            if (t4 == 0)      src = g_xh + xrow0 + (size_t)r * D_ + k0 + j * 8;
            else if (t4 == 1) src = g_xl + xrow0 + (size_t)r * D_ + k0 + j * 8;
            else {
                int wr = (r < 64) ? (h * HD_ + r) : (448 + h * HD_ + r);
                src = ((t4 == 2) ? g_Wh : g_Wl) + (size_t)wr * D_ + k0 + j * 8;
            }
            __pipeline_memcpy_async(dst, src, 16);
        }
    };

    prefetch(0, 0);
    __pipeline_commit();

    for (int c = 0; c < NCH_; c++) {
        const int s = c & 1;
        if (c + 1 < NCH_) {
            prefetch(c + 1, s ^ 1);
            __pipeline_commit();
            __pipeline_wait_prior(1);
        } else {
            __pipeline_wait_prior(0);
        }
        __syncthreads();
        mma_chunk(smem, s, m0, n0, acc);
        __syncthreads();
    }

    // epilogue: acc -> KV smem [128][132] fp32
    float* KV = reinterpret_cast<float*>(smem);
    #pragma unroll
    for (int mt = 0; mt < 2; mt++)
        #pragma unroll
        for (int nt = 0; nt < 4; nt++)
            wmma::store_matrix_sync(KV + (m0 + mt * 16) * 132 + n0 + nt * 16,
                                    acc[mt][nt], 132, wmma::mem_row_major);
    __syncthreads();

    // bias + exp on k-half
    #pragma unroll
    for (int i = 0; i < 64; i++) {
        int flat = i * 256 + tid;
        int r = flat >> 7, cc = flat & 127;
        float v = KV[r * 132 + cc];
        if (cc < 64) v = expf(v + bqkv[wrow_k + cc]);
        else         v = v + bqkv[wrow_v + cc - 64];
        KV[r * 132 + cc] = v;
    }
    __syncthreads();

    // U = EK^T @ V (16x16 threads, 4x4 micro)
    const int tx = tid & 15, ty = tid >> 4;
    float u[4][4];
    #pragma unroll
    for (int dd = 0; dd < 4; dd++)
        #pragma unroll
        for (int vv = 0; vv < 4; vv++) u[dd][vv] = 0.f;
    for (int t = 0; t < TT_; t++) {
        float a_[4], b_[4];
        #pragma unroll
        for (int dd = 0; dd < 4; dd++) a_[dd] = KV[t * 132 + ty * 4 + dd];
        #pragma unroll
        for (int vv = 0; vv < 4; vv++) b_[vv] = KV[t * 132 + 64 + tx * 4 + vv];
        #pragma unroll
        for (int dd = 0; dd < 4; dd++)
            #pragma unroll
            for (int vv = 0; vv < 4; vv++) u[dd][vv] += a_[dd] * b_[vv];
    }
    size_t ubase = (size_t)((b * NTILE_ + tile) * H_ + h) * (HD_ * HD_);
    #pragma unroll
    for (int dd = 0; dd < 4; dd++)
        #pragma unroll
        for (int vv = 0; vv < 4; vv++)
            g_Upart[ubase + (ty * 4 + dd) * HD_ + tx * 4 + vv] = u[dd][vv];
    if (tid < 64) {
        float ssum = 0.f;
        for (int t = 0; t < TT_; t++) ssum += KV[t * 132 + tid];
        g_Spart[((b * NTILE_ + tile) * H_ + h) * HD_ + tid] = ssum;
    }
}

// =====================================================================
// K2: reduce partials -> C = U / S  (unchanged)
// =====================================================================
__global__ void k2_reduce()
{
    const int b = blockIdx.x >> 3, h = blockIdx.x & 7;
    const int tid = threadIdx.x;
    __shared__ float S[64];
    if (tid < 64) {
        float s = 0.f;
        for (int t = 0; t < NTILE_; t++)
            s += g_Spart[((b * NTILE_ + t) * H_ + h) * HD_ + tid];
        S[tid] = s;
    }
    __syncthreads();
    for (int e = tid; e < HD_ * HD_; e += 256) {
        float u = 0.f;
        #pragma unroll 8
        for (int t = 0; t < NTILE_; t++)
            u += g_Upart[(size_t)((b * NTILE_ + t) * H_ + h) * (HD_ * HD_) + e];
        g_C[(b * H_ + h) * (HD_ * HD_) + e] = u / S[e >> 6];
    }
}

// =====================================================================
// K3: A[b][j][i]  (unchanged)
// =====================================================================
__global__ void k3_A(const float* __restrict__ Wqkv)
{
    const int b = blockIdx.x >> 3, h = blockIdx.x & 7;
    const int tid = threadIdx.x;
    __shared__ float Ch[64 * 64];
    __shared__ float Wc[64 * 128];
    for (int e = tid; e < 4096; e += 256)
        Ch[e] = g_C[(b * H_ + h) * 4096 + e];
    for (int chunk = 0; chunk < 4; chunk++) {
        int i0 = chunk * 128;
        __syncthreads();
        for (int e = tid; e < 64 * 128; e += 256) {
            int d = e >> 7, ii = e & 127;
            Wc[e] = Wqkv[(size_t)(h * HD_ + d) * D_ + i0 + ii];
        }
        __syncthreads();
        for (int idx = tid; idx < 64 * 128; idx += 256) {
            int vv = idx >> 7, ii = idx & 127;
            float s = 0.f;
            #pragma unroll
            for (int d = 0; d < 64; d++) s += Ch[d * 64 + vv] * Wc[d * 128 + ii];
            g_A[(size_t)b * (D_ * D_) + (size_t)(h * HD_ + vv) * D_ + i0 + ii] = s;
        }
    }
}

__global__ void k3b_pb(const float* __restrict__ bqkv)
{
    const int b = blockIdx.x;
    const int j = threadIdx.x;
    const int h = j >> 6, vv = j & 63;
    float s = 0.f;
    for (int d = 0; d < 64; d++)
        s += bqkv[h * HD_ + d] * g_C[(b * H_ + h) * 4096 + d * 64 + vv];
    g_pb[b * D_ + j] = s;
}

// =====================================================================
// K4: E GEMM (SIMT fp32) -> writes E^T [b][o][i] as bf16 hi/lo.
// =====================================================================
__global__ __launch_bounds__(256, 2)
void k4_E(const float* __restrict__ Wout)
{
    const int tid = threadIdx.x;
    const int tx = tid & 15, ty = tid >> 4;
    const int i0 = blockIdx.x * 128, o0 = blockIdx.y * 128, b = blockIdx.z;
    __shared__ float Xs[128 * 17];
    __shared__ float Ws[128 * 17];
    const float* Ab = g_A + (size_t)b * (D_ * D_);

    float acc[8][8];
    #pragma unroll
    for (int r = 0; r < 8; r++)
        #pragma unroll
        for (int c = 0; c < 8; c++) acc[r][c] = 0.f;

    for (int j0 = 0; j0 < D_; j0 += 16) {
        #pragma unroll
        for (int q = 0; q < 2; q++) {
            int flat = tid * 2 + q;
            int jj = flat >> 5;
            int ii = (flat & 31) * 4;
            float4 t = *reinterpret_cast<const float4*>(Ab + (size_t)(j0 + jj) * D_ + i0 + ii);
            Xs[(ii + 0) * 17 + jj] = t.x;
            Xs[(ii + 1) * 17 + jj] = t.y;
            Xs[(ii + 2) * 17 + jj] = t.z;
            Xs[(ii + 3) * 17 + jj] = t.w;
        }
        #pragma unroll
        for (int q = 0; q < 2; q++) {
            int flat = tid * 2 + q;
            int col = flat >> 2;
            int c4 = (flat & 3) * 4;
            float4 t = *reinterpret_cast<const float4*>(Wout + (size_t)(o0 + col) * D_ + j0 + c4);
            float* dst = Ws + col * 17 + c4;
            dst[0] = t.x; dst[1] = t.y; dst[2] = t.z; dst[3] = t.w;
        }
        __syncthreads();
        #pragma unroll
        for (int kk = 0; kk < 16; kk++) {
            float a_[8], b_[8];
            #pragma unroll
            for (int r = 0; r < 8; r++) a_[r] = Xs[(ty * 8 + r) * 17 + kk];
            #pragma unroll
            for (int c = 0; c < 8; c++) b_[c] = Ws[(tx + 16 * c) * 17 + kk];
            #pragma unroll
            for (int r = 0; r < 8; r++)
                #pragma unroll
                for (int c = 0; c < 8; c++) acc[r][c] += a_[r] * b_[c];
        }
        __syncthreads();
    }
    // E^T bf16 hi/lo store: row o, 8 consecutive i per thread (4 bf16x2 pairs each)
    #pragma unroll
    for (int c = 0; c < 8; c++) {
        int o = o0 + tx + 16 * c;
        size_t base = ((size_t)b * D_ + o) * D_ + i0 + ty * 8;
        #pragma unroll
        for (int p = 0; p < 4; p++) {
            float e0 = acc[2 * p][c], e1 = acc[2 * p + 1][c];
            __nv_bfloat162 hi = __floats2bfloat162_rn(e0, e1);
            __nv_bfloat162 lo = __floats2bfloat162_rn(e0 - __low2float(hi), e1 - __high2float(hi));
            *reinterpret_cast<__nv_bfloat162*>(g_Eth + base + 2 * p) = hi;
            *reinterpret_cast<__nv_bfloat162*>(g_Etl + base + 2 * p) = lo;
        }
    }
}

__global__ void k4b_bias(const float* __restrict__ Wout, const float* __restrict__ bout)
{
    const int b = blockIdx.x;
    const int o = threadIdx.x;
    float s = bout[o];
    const float* wr = Wout + (size_t)o * D_;
    const float* pb = g_pb + b * D_;
    #pragma unroll 8
    for (int j = 0; j < D_; j++) s += pb[j] * wr[j];
    g_bias[b * D_ + o] = s;
}

// =====================================================================
// K5: out = x @ E_b + bias, WMMA split-bf16, cp.async pipelined.
// =====================================================================
__global__ __launch_bounds__(256)
void k5_out(float* __restrict__ out)
{
    extern __shared__ __align__(128) char smem[];
    const int tid = threadIdx.x, wid = tid >> 5;
    const int t0 = blockIdx.x * TT_, o0 = blockIdx.y * 128, b = blockIdx.z;
    const size_t xrow0 = (size_t)(b * T_ + t0) * D_;
    const size_t erow0 = ((size_t)b * D_ + o0) * D_;

    const int m0 = (wid >> 1) * 32;
    const int n0 = (wid & 1) * 64;

    FragC acc[2][4];
    #pragma unroll
    for (int mt = 0; mt < 2; mt++)
        #pragma unroll
        for (int nt = 0; nt < 4; nt++) wmma::fill_fragment(acc[mt][nt], 0.f);

    auto prefetch = [&](int c, int s) {
        const int k0 = c * KC_;
        #pragma unroll
        for (int q = 0; q < 8; q++) {
            int flat = q * 256 + tid;
            int t4 = flat >> 9;
            int w = flat & 511;
            int r = w >> 2, j = w & 3;
            char* dst = smem + BTOFF_(s, t4) + (uint32_t)r * (LDS_ * 2) + (uint32_t)j * 16;
            const __nv_bfloat16* src;
            if (t4 == 0)      src = g_xh + xrow0 + (size_t)r * D_ + k0 + j * 8;
            else if (t4 == 1) src = g_xl + xrow0 + (size_t)r * D_ + k0 + j * 8;
            else if (t4 == 2) src = g_Eth + erow0 + (size_t)r * D_ + k0 + j * 8;
            else              src = g_Etl + erow0 + (size_t)r * D_ + k0 + j * 8;
            __pipeline_memcpy_async(dst, src, 16);
        }
    };

    prefetch(0, 0);
    __pipeline_commit();

    for (int c = 0; c < NCH_; c++) {
        const int s = c & 1;
        if (c + 1 < NCH_) {
            prefetch(c + 1, s ^ 1);
            __pipeline_commit();
            __pipeline_wait_prior(1);
        } else {
            __pipeline_wait_prior(0);
        }
        __syncthreads();
        mma_chunk(smem, s, m0, n0, acc);
        __syncthreads();
    }

    // epilogue: acc -> smem stage -> +bias -> coalesced fp32 stores
    float* Stage = reinterpret_cast<float*>(smem);   // [128][132]
    #pragma unroll
    for (int mt = 0; mt < 2; mt++)
        #pragma unroll
        for (int nt = 0; nt < 4; nt++)
            wmma::store_matrix_sync(Stage + (m0 + mt * 16) * 132 + n0 + nt * 16,
                                    acc[mt][nt], 132, wmma::mem_row_major);
    __syncthreads();

    #pragma unroll
    for (int q = 0; q < 16; q++) {
        int flat = q * 256 + tid;
        int r = flat >> 5, j = flat & 31;
        float4 v = *reinterpret_cast<const float4*>(Stage + r * 132 + j * 4);
        float4 bias = *reinterpret_cast<const float4*>(g_bias + b * D_ + o0 + j * 4);
        v.x += bias.x; v.y += bias.y; v.z += bias.z; v.w += bias.w;
        *reinterpret_cast<float4*>(out + (size_t)(b * T_ + t0 + r) * D_ + o0 + j * 4) = v;
    }
}

// =====================================================================
extern "C" void kernel_launch(void* const* d_in, const int* in_sizes, int n_in,
                              void* d_out, int out_size)
{
    (void)in_sizes; (void)n_in; (void)out_size;
    const float* x    = (const float*)d_in[0];
    const float* Wqkv = (const float*)d_in[1];
    const float* bqkv = (const float*)d_in[2];
    const float* Wout = (const float*)d_in[3];
    const float* bout = (const float*)d_in[4];
    float* out = (float*)d_out;

    cudaFuncSetAttribute(k1_kv_context, cudaFuncAttributeMaxDynamicSharedMemorySize, WSMEM_);
    cudaFuncSetAttribute(k5_out, cudaFuncAttributeMaxDynamicSharedMemorySize, WSMEM_);

    kx_xsplit<<<(B_ * T_ * D_) / (256 * 4), 256>>>(x);
    k0_wsplit<<<(1024 * D_) / 256, 256>>>(Wqkv);
    k1_kv_context<<<dim3(NTILE_, H_, B_), 256, WSMEM_>>>(bqkv);
    k2_reduce<<<B_ * H_, 256>>>();
    k3_A<<<B_ * H_, 256>>>(Wqkv);
    k3b_pb<<<B_, D_>>>(bqkv);
    k4_E<<<dim3(4, 4, B_), 256>>>(Wout);
    k4b_bias<<<B_, D_>>>(Wout, bout);
    k5_out<<<dim3(NTILE_, 4, B_), 256, WSMEM_>>>(out);
}

// round 17
// speedup vs baseline: 1.1946x; 1.1224x over previous
#include <cuda_runtime.h>
#include <cuda_bf16.h>
#include <mma.h>
#include <math.h>
#include <stdint.h>

using namespace nvcuda;

// LinearSelfAttention: B=4, T=8192, D=512, H=8, HD=64
// Round-11 source (1030us PASS, best) with ONE change: k2_reduce replaced by
// a parallel two-stage reduction (k2a_S + k2b_U). ncu showed k2 at 88us /
// 12% occ / 386GB/s — parallelism-starved; this brings it to stream bandwidth.

#define B_ 4
#define T_ 8192
#define D_ 512
#define H_ 8
#define HD_ 64
#define TT_ 128            // token tile
#define NTILE_ (T_ / TT_)  // 64
#define KC_ 32             // k-chunk
#define NCH_ (D_ / KC_)    // 16
#define LDS_ 48            // smem row stride in bf16 (96B rows)

// ---------------- scratch (device globals; no allocs) ----------------
__device__ __align__(128) float g_Upart[B_ * NTILE_ * H_ * HD_ * HD_]; // 32 MB
__device__ __align__(128) float g_Spart[B_ * NTILE_ * H_ * HD_];
__device__ __align__(128) float g_S[B_ * H_ * HD_];
__device__ __align__(128) float g_C[B_ * H_ * HD_ * HD_];
__device__ __align__(128) float g_A[B_ * D_ * D_];
__device__ __align__(128) float g_Et[B_ * D_ * D_];                    // E^T [b][o][i]
__device__ __align__(128) float g_pb[B_ * D_];
__device__ __align__(128) float g_bias[B_ * D_];

#define TILE_BYTES_ (128 * LDS_ * 2)                       // 12288
#define BTOFF_(s, t4) ((uint32_t)(s) * (4 * TILE_BYTES_) + (uint32_t)(t4) * TILE_BYTES_)
#define WSMEM_ (2 * 4 * TILE_BYTES_)                       // 98304

typedef wmma::fragment<wmma::matrix_a, 16, 16, 16, __nv_bfloat16, wmma::row_major> FragA;
typedef wmma::fragment<wmma::matrix_b, 16, 16, 16, __nv_bfloat16, wmma::col_major> FragB;
typedef wmma::fragment<wmma::accumulator, 16, 16, 16, float> FragC;

// convert float4 -> bf16 hi/lo pairs and store 8B each
__device__ __forceinline__ void split_store(__nv_bfloat16* Hi, __nv_bfloat16* Lo,
                                            int e, float4 v)
{
    __nv_bfloat162 h0 = __floats2bfloat162_rn(v.x, v.y);
    __nv_bfloat162 h1 = __floats2bfloat162_rn(v.z, v.w);
    __nv_bfloat162 l0 = __floats2bfloat162_rn(v.x - __low2float(h0), v.y - __high2float(h0));
    __nv_bfloat162 l1 = __floats2bfloat162_rn(v.z - __low2float(h1), v.w - __high2float(h1));
    *reinterpret_cast<__nv_bfloat162*>(Hi + e)     = h0;
    *reinterpret_cast<__nv_bfloat162*>(Hi + e + 2) = h1;
    *reinterpret_cast<__nv_bfloat162*>(Lo + e)     = l0;
    *reinterpret_cast<__nv_bfloat162*>(Lo + e + 2) = l1;
}

// =====================================================================
// K1: WMMA split-bf16 KV projection + exp + U/S. Double-buffered staging.
// grid (64 tiles, 8 heads, 4 b), block 256 (8 warps, warp tile 32x64).
// =====================================================================
__global__ __launch_bounds__(256)
void k1_kv_context(const float* __restrict__ x,
                   const float* __restrict__ Wqkv,
                   const float* __restrict__ bqkv)
{
    extern __shared__ __align__(128) char smem[];
    const int tid = threadIdx.x, wid = tid >> 5;
    const int tile = blockIdx.x, h = blockIdx.y, b = blockIdx.z;
    const float* xb = x + (size_t)(b * T_ + tile * TT_) * D_;
    const int wrow_k = D_ + h * HD_;
    const int wrow_v = 2 * D_ + h * HD_;

    const int m0 = (wid >> 1) * 32;
    const int n0 = (wid & 1) * 64;

    FragC acc[2][4];
    #pragma unroll
    for (int mt = 0; mt < 2; mt++)
        #pragma unroll
        for (int nt = 0; nt < 4; nt++) wmma::fill_fragment(acc[mt][nt], 0.f);

    auto stage = [&](int c, int s) {
        const int k0 = c * KC_;
        __nv_bfloat16* Ah = reinterpret_cast<__nv_bfloat16*>(smem + BTOFF_(s, 0));
        __nv_bfloat16* Al = reinterpret_cast<__nv_bfloat16*>(smem + BTOFF_(s, 1));
        __nv_bfloat16* Bh = reinterpret_cast<__nv_bfloat16*>(smem + BTOFF_(s, 2));
        __nv_bfloat16* Bl = reinterpret_cast<__nv_bfloat16*>(smem + BTOFF_(s, 3));
        #pragma unroll
        for (int q = 0; q < 4; q++) {           // x: [128 t][32 i]
            int flat = q * 256 + tid;           // 0..1023 float4s
            int r = flat >> 3, j = flat & 7;
            float4 v = *reinterpret_cast<const float4*>(xb + (size_t)r * D_ + k0 + j * 4);
            split_store(Ah, Al, r * LDS_ + j * 4, v);
        }
        #pragma unroll
        for (int q = 0; q < 4; q++) {           // W: [128 cols][32 k]
            int flat = q * 256 + tid;
            int col = flat >> 3, j = flat & 7;
            int wrow = (col < 64) ? (wrow_k + col) : (wrow_v + col - 64);
            float4 w = *reinterpret_cast<const float4*>(Wqkv + (size_t)wrow * D_ + k0 + j * 4);
            split_store(Bh, Bl, col * LDS_ + j * 4, w);
        }
    };

    stage(0, 0);
    __syncthreads();

    for (int c = 0; c < NCH_; c++) {
        const int s = c & 1;
        if (c + 1 < NCH_) stage(c + 1, s ^ 1);   // overlaps with MMA below
        const __nv_bfloat16* Ah = reinterpret_cast<const __nv_bfloat16*>(smem + BTOFF_(s, 0));
        const __nv_bfloat16* Al = reinterpret_cast<const __nv_bfloat16*>(smem + BTOFF_(s, 1));
        const __nv_bfloat16* Bh = reinterpret_cast<const __nv_bfloat16*>(smem + BTOFF_(s, 2));
        const __nv_bfloat16* Bl = reinterpret_cast<const __nv_bfloat16*>(smem + BTOFF_(s, 3));
        #pragma unroll
        for (int ks = 0; ks < KC_; ks += 16) {
            FragA fah[2], fal[2];
            FragB fbh[4], fbl[4];
            #pragma unroll
            for (int mt = 0; mt < 2; mt++) {
                wmma::load_matrix_sync(fah[mt], Ah + (m0 + mt * 16) * LDS_ + ks, LDS_);
                wmma::load_matrix_sync(fal[mt], Al + (m0 + mt * 16) * LDS_ + ks, LDS_);
            }
            #pragma unroll
            for (int nt = 0; nt < 4; nt++) {
                wmma::load_matrix_sync(fbh[nt], Bh + (n0 + nt * 16) * LDS_ + ks, LDS_);
                wmma::load_matrix_sync(fbl[nt], Bl + (n0 + nt * 16) * LDS_ + ks, LDS_);
            }
            #pragma unroll
            for (int mt = 0; mt < 2; mt++)
                #pragma unroll
                for (int nt = 0; nt < 4; nt++) {
                    wmma::mma_sync(acc[mt][nt], fah[mt], fbh[nt], acc[mt][nt]);
                    wmma::mma_sync(acc[mt][nt], fah[mt], fbl[nt], acc[mt][nt]);
                    wmma::mma_sync(acc[mt][nt], fal[mt], fbh[nt], acc[mt][nt]);
                }
        }
        __syncthreads();   // MMA on buf s done; stores to buf s^1 complete
    }

    // epilogue: acc -> KV smem [128][132] fp32
    float* KV = reinterpret_cast<float*>(smem);
    #pragma unroll
    for (int mt = 0; mt < 2; mt++)
        #pragma unroll
        for (int nt = 0; nt < 4; nt++)
            wmma::store_matrix_sync(KV + (m0 + mt * 16) * 132 + n0 + nt * 16,
                                    acc[mt][nt], 132, wmma::mem_row_major);
    __syncthreads();

    // bias + exp on k-half
    #pragma unroll
    for (int i = 0; i < 64; i++) {
        int flat = i * 256 + tid;
        int r = flat >> 7, cc = flat & 127;
        float v = KV[r * 132 + cc];
        if (cc < 64) v = expf(v + bqkv[wrow_k + cc]);
        else         v = v + bqkv[wrow_v + cc - 64];
        KV[r * 132 + cc] = v;
    }
    __syncthreads();

    // U = EK^T @ V (16x16 threads, 4x4 micro)
    const int tx = tid & 15, ty = tid >> 4;
    float u[4][4];
    #pragma unroll
    for (int dd = 0; dd < 4; dd++)
        #pragma unroll
        for (int vv = 0; vv < 4; vv++) u[dd][vv] = 0.f;
    for (int t = 0; t < TT_; t++) {
        float a_[4], b_[4];
        #pragma unroll
        for (int dd = 0; dd < 4; dd++) a_[dd] = KV[t * 132 + ty * 4 + dd];
        #pragma unroll
        for (int vv = 0; vv < 4; vv++) b_[vv] = KV[t * 132 + 64 + tx * 4 + vv];
        #pragma unroll
        for (int dd = 0; dd < 4; dd++)
            #pragma unroll
            for (int vv = 0; vv < 4; vv++) u[dd][vv] += a_[dd] * b_[vv];
    }
    size_t ubase = (size_t)((b * NTILE_ + tile) * H_ + h) * (HD_ * HD_);
    #pragma unroll
    for (int dd = 0; dd < 4; dd++)
        #pragma unroll
        for (int vv = 0; vv < 4; vv++)
            g_Upart[ubase + (ty * 4 + dd) * HD_ + tx * 4 + vv] = u[dd][vv];
    if (tid < 64) {
        float ssum = 0.f;
        for (int t = 0; t < TT_; t++) ssum += KV[t * 132 + tid];
        g_Spart[((b * NTILE_ + tile) * H_ + h) * HD_ + tid] = ssum;
    }
}

// =====================================================================
// K2a: S[b][h][d] = sum_tiles Spart  (tiny)
// grid 32 (b*h), block 64
// =====================================================================
__global__ void k2a_S()
{
    const int b = blockIdx.x >> 3, h = blockIdx.x & 7;
    const int d = threadIdx.x;
    float s = 0.f;
    #pragma unroll 8
    for (int t = 0; t < NTILE_; t++)
        s += g_Spart[((b * NTILE_ + t) * H_ + h) * HD_ + d];
    g_S[(b * H_ + h) * HD_ + d] = s;
}

// =====================================================================
// K2b: C = (sum_tiles Upart) / S, parallel.
// grid (32 bh, 8 chunks), block 128; each thread: one float4 across 64 tiles.
// =====================================================================
__global__ __launch_bounds__(128)
void k2b_U()
{
    const int bh = blockIdx.x;             // 0..31
    const int b = bh >> 3, h = bh & 7;
    const int e0 = blockIdx.y * 512 + threadIdx.x * 4;   // element offset in 64x64
    float4 u = make_float4(0.f, 0.f, 0.f, 0.f);
    #pragma unroll 4
    for (int t = 0; t < NTILE_; t++) {
        const float4 v = *reinterpret_cast<const float4*>(
            g_Upart + (size_t)((b * NTILE_ + t) * H_ + h) * (HD_ * HD_) + e0);
        u.x += v.x; u.y += v.y; u.z += v.z; u.w += v.w;
    }
    const float s = g_S[(b * H_ + h) * HD_ + (e0 >> 6)];
    u.x /= s; u.y /= s; u.z /= s; u.w /= s;
    *reinterpret_cast<float4*>(g_C + (bh) * (HD_ * HD_) + e0) = u;
}

// =====================================================================
// K3: A[b][j][i]  (unchanged)
// =====================================================================
__global__ void k3_A(const float* __restrict__ Wqkv)
{
    const int b = blockIdx.x >> 3, h = blockIdx.x & 7;
    const int tid = threadIdx.x;
    __shared__ float Ch[64 * 64];
    __shared__ float Wc[64 * 128];
    for (int e = tid; e < 4096; e += 256)
        Ch[e] = g_C[(b * H_ + h) * 4096 + e];
    for (int chunk = 0; chunk < 4; chunk++) {
        int i0 = chunk * 128;
        __syncthreads();
        for (int e = tid; e < 64 * 128; e += 256) {
            int d = e >> 7, ii = e & 127;
            Wc[e] = Wqkv[(size_t)(h * HD_ + d) * D_ + i0 + ii];
        }
        __syncthreads();
        for (int idx = tid; idx < 64 * 128; idx += 256) {
            int vv = idx >> 7, ii = idx & 127;
            float s = 0.f;
            #pragma unroll
            for (int d = 0; d < 64; d++) s += Ch[d * 64 + vv] * Wc[d * 128 + ii];
            g_A[(size_t)b * (D_ * D_) + (size_t)(h * HD_ + vv) * D_ + i0 + ii] = s;
        }
    }
}

__global__ void k3b_pb(const float* __restrict__ bqkv)
{
    const int b = blockIdx.x;
    const int j = threadIdx.x;
    const int h = j >> 6, vv = j & 63;
    float s = 0.f;
    for (int d = 0; d < 64; d++)
        s += bqkv[h * HD_ + d] * g_C[(b * H_ + h) * 4096 + d * 64 + vv];
    g_pb[b * D_ + j] = s;
}

// =====================================================================
// K4: E^T [b][o][i] fp32, float4 stores along i  (unchanged)
// =====================================================================
__global__ __launch_bounds__(256, 2)
void k4_E(const float* __restrict__ Wout)
{
    const int tid = threadIdx.x;
    const int tx = tid & 15, ty = tid >> 4;
    const int i0 = blockIdx.x * 128, o0 = blockIdx.y * 128, b = blockIdx.z;
    __shared__ float Xs[128 * 17];
    __shared__ float Ws[128 * 17];
    const float* Ab = g_A + (size_t)b * (D_ * D_);

    float acc[8][8];
    #pragma unroll
    for (int r = 0; r < 8; r++)
        #pragma unroll
        for (int c = 0; c < 8; c++) acc[r][c] = 0.f;

    for (int j0 = 0; j0 < D_; j0 += 16) {
        #pragma unroll
        for (int q = 0; q < 2; q++) {
            int flat = tid * 2 + q;
            int jj = flat >> 5;
            int ii = (flat & 31) * 4;
            float4 t = *reinterpret_cast<const float4*>(Ab + (size_t)(j0 + jj) * D_ + i0 + ii);
            Xs[(ii + 0) * 17 + jj] = t.x;
            Xs[(ii + 1) * 17 + jj] = t.y;
            Xs[(ii + 2) * 17 + jj] = t.z;
            Xs[(ii + 3) * 17 + jj] = t.w;
        }
        #pragma unroll
        for (int q = 0; q < 2; q++) {
            int flat = tid * 2 + q;
            int col = flat >> 2;
            int c4 = (flat & 3) * 4;
            float4 t = *reinterpret_cast<const float4*>(Wout + (size_t)(o0 + col) * D_ + j0 + c4);
            float* dst = Ws + col * 17 + c4;
            dst[0] = t.x; dst[1] = t.y; dst[2] = t.z; dst[3] = t.w;
        }
        __syncthreads();
        #pragma unroll
        for (int kk = 0; kk < 16; kk++) {
            float a_[8], b_[8];
            #pragma unroll
            for (int r = 0; r < 8; r++) a_[r] = Xs[(ty * 8 + r) * 17 + kk];
            #pragma unroll
            for (int c = 0; c < 8; c++) b_[c] = Ws[(tx + 16 * c) * 17 + kk];
            #pragma unroll
            for (int r = 0; r < 8; r++)
                #pragma unroll
                for (int c = 0; c < 8; c++) acc[r][c] += a_[r] * b_[c];
        }
        __syncthreads();
    }
    float* Eb = g_Et + (size_t)b * (D_ * D_);
    #pragma unroll
    for (int c = 0; c < 8; c++) {
        int o = o0 + tx + 16 * c;
        float4 v0 = make_float4(acc[0][c], acc[1][c], acc[2][c], acc[3][c]);
        float4 v1 = make_float4(acc[4][c], acc[5][c], acc[6][c], acc[7][c]);
        *reinterpret_cast<float4*>(Eb + (size_t)o * D_ + i0 + ty * 8)     = v0;
        *reinterpret_cast<float4*>(Eb + (size_t)o * D_ + i0 + ty * 8 + 4) = v1;
    }
}

__global__ void k4b_bias(const float* __restrict__ Wout, const float* __restrict__ bout)
{
    const int b = blockIdx.x;
    const int o = threadIdx.x;
    float s = bout[o];
    const float* wr = Wout + (size_t)o * D_;
    const float* pb = g_pb + b * D_;
    #pragma unroll 8
    for (int j = 0; j < D_; j++) s += pb[j] * wr[j];
    g_bias[b * D_ + o] = s;
}

// =====================================================================
// K5: out = x @ E_b + bias, WMMA split-bf16, double-buffered staging.
// (round-11 verbatim)
// =====================================================================
__global__ __launch_bounds__(256)
void k5_out(const float* __restrict__ x, float* __restrict__ out)
{
    extern __shared__ __align__(128) char smem[];
    const int tid = threadIdx.x, wid = tid >> 5;
    const int t0 = blockIdx.x * TT_, o0 = blockIdx.y * 128, b = blockIdx.z;
    const float* xb = x + (size_t)(b * T_ + t0) * D_;
    const float* Eb = g_Et + (size_t)b * (D_ * D_);

    const int m0 = (wid >> 1) * 32;
    const int n0 = (wid & 1) * 64;

    FragC acc[2][4];
    #pragma unroll
    for (int mt = 0; mt < 2; mt++)
        #pragma unroll
        for (int nt = 0; nt < 4; nt++) wmma::fill_fragment(acc[mt][nt], 0.f);

    auto stage = [&](int c, int s) {
        const int k0 = c * KC_;
        __nv_bfloat16* Ah = reinterpret_cast<__nv_bfloat16*>(smem + BTOFF_(s, 0));
        __nv_bfloat16* Al = reinterpret_cast<__nv_bfloat16*>(smem + BTOFF_(s, 1));
        __nv_bfloat16* Bh = reinterpret_cast<__nv_bfloat16*>(smem + BTOFF_(s, 2));
        __nv_bfloat16* Bl = reinterpret_cast<__nv_bfloat16*>(smem + BTOFF_(s, 3));
        #pragma unroll
        for (int q = 0; q < 4; q++) {           // x
            int flat = q * 256 + tid;
            int r = flat >> 3, j = flat & 7;
            float4 v = *reinterpret_cast<const float4*>(xb + (size_t)r * D_ + k0 + j * 4);
            split_store(Ah, Al, r * LDS_ + j * 4, v);
        }
        #pragma unroll
        for (int q = 0; q < 4; q++) {           // E^T rows: [128 o][32 i]
            int flat = q * 256 + tid;
            int o = flat >> 3, j = flat & 7;
            float4 v = *reinterpret_cast<const float4*>(Eb + (size_t)(o0 + o) * D_ + k0 + j * 4);
            split_store(Bh, Bl, o * LDS_ + j * 4, v);
        }
    };

    stage(0, 0);
    __syncthreads();

    for (int c = 0; c < NCH_; c++) {
        const int s = c & 1;
        if (c + 1 < NCH_) stage(c + 1, s ^ 1);
        const __nv_bfloat16* Ah = reinterpret_cast<const __nv_bfloat16*>(smem + BTOFF_(s, 0));
        const __nv_bfloat16* Al = reinterpret_cast<const __nv_bfloat16*>(smem + BTOFF_(s, 1));
        const __nv_bfloat16* Bh = reinterpret_cast<const __nv_bfloat16*>(smem + BTOFF_(s, 2));
        const __nv_bfloat16* Bl = reinterpret_cast<const __nv_bfloat16*>(smem + BTOFF_(s, 3));
        #pragma unroll
        for (int ks = 0; ks < KC_; ks += 16) {
            FragA fah[2], fal[2];
            FragB fbh[4], fbl[4];
            #pragma unroll
            for (int mt = 0; mt < 2; mt++) {
                wmma::load_matrix_sync(fah[mt], Ah + (m0 + mt * 16) * LDS_ + ks, LDS_);
                wmma::load_matrix_sync(fal[mt], Al + (m0 + mt * 16) * LDS_ + ks, LDS_);
            }
            #pragma unroll
            for (int nt = 0; nt < 4; nt++) {
                wmma::load_matrix_sync(fbh[nt], Bh + (n0 + nt * 16) * LDS_ + ks, LDS_);
                wmma::load_matrix_sync(fbl[nt], Bl + (n0 + nt * 16) * LDS_ + ks, LDS_);
            }
            #pragma unroll
            for (int mt = 0; mt < 2; mt++)
                #pragma unroll
                for (int nt = 0; nt < 4; nt++) {
                    wmma::mma_sync(acc[mt][nt], fah[mt], fbh[nt], acc[mt][nt]);
                    wmma::mma_sync(acc[mt][nt], fah[mt], fbl[nt], acc[mt][nt]);
                    wmma::mma_sync(acc[mt][nt], fal[mt], fbh[nt], acc[mt][nt]);
                }
        }
        __syncthreads();
    }

    // epilogue: acc -> smem stage -> +bias -> coalesced fp32 stores
    float* Stage = reinterpret_cast<float*>(smem);   // [128][132]
    #pragma unroll
    for (int mt = 0; mt < 2; mt++)
        #pragma unroll
        for (int nt = 0; nt < 4; nt++)
            wmma::store_matrix_sync(Stage + (m0 + mt * 16) * 132 + n0 + nt * 16,
                                    acc[mt][nt], 132, wmma::mem_row_major);
    __syncthreads();

    #pragma unroll
    for (int q = 0; q < 16; q++) {
        int flat = q * 256 + tid;
        int r = flat >> 5, j = flat & 31;
        float4 v = *reinterpret_cast<const float4*>(Stage + r * 132 + j * 4);
        float4 bias = *reinterpret_cast<const float4*>(g_bias + b * D_ + o0 + j * 4);
        v.x += bias.x; v.y += bias.y; v.z += bias.z; v.w += bias.w;
        *reinterpret_cast<float4*>(out + (size_t)(b * T_ + t0 + r) * D_ + o0 + j * 4) = v;
    }
}

// =====================================================================
extern "C" void kernel_launch(void* const* d_in, const int* in_sizes, int n_in,
                              void* d_out, int out_size)
{
    (void)in_sizes; (void)n_in; (void)out_size;
    const float* x    = (const float*)d_in[0];
    const float* Wqkv = (const float*)d_in[1];
    const float* bqkv = (const float*)d_in[2];
    const float* Wout = (const float*)d_in[3];
    const float* bout = (const float*)d_in[4];
    float* out = (float*)d_out;

    cudaFuncSetAttribute(k1_kv_context, cudaFuncAttributeMaxDynamicSharedMemorySize, WSMEM_);
    cudaFuncSetAttribute(k5_out, cudaFuncAttributeMaxDynamicSharedMemorySize, WSMEM_);

    k1_kv_context<<<dim3(NTILE_, H_, B_), 256, WSMEM_>>>(x, Wqkv, bqkv);
    k2a_S<<<B_ * H_, 64>>>();
    k2b_U<<<dim3(B_ * H_, 8), 128>>>();
    k3_A<<<B_ * H_, 256>>>(Wqkv);
    k3b_pb<<<B_, D_>>>(bqkv);
    k4_E<<<dim3(4, 4, B_), 256>>>(Wout);
    k4b_bias<<<B_, D_>>>(Wout, bout);
    k5_out<<<dim3(NTILE_, 4, B_), 256, WSMEM_>>>(x, out);
}